// round 11
// baseline (speedup 1.0000x reference)
#include <cuda_runtime.h>
#include <cuda_bf16.h>
#include <cub/block/block_radix_sort.cuh>
#include <cstdint>

#define B_SZ   8
#define NFULL  4096
#define NLAT   1024
#define CDIM   256
#define HEADS  8
#define VDIM   32

// ---------------- scratch (static device arrays; no allocation) ----------------
__device__ float g_bufA[B_SZ * NFULL * CDIM];   // h0 hi/lo (bf16 pairs), later up-att out
__device__ float g_bufB[B_SZ * NFULL * CDIM];   // de1 out fp32
__device__ float g_bufL0[B_SZ * NLAT * CDIM];
__device__ float g_bufL1[B_SZ * NLAT * CDIM];
__device__ float g_bufL2[B_SZ * NLAT * CDIM];
__device__ float g_mlp [B_SZ * NLAT * CDIM];
__device__ float g_att [HEADS * NFULL * NLAT];  // att hi/lo bf16 pairs
__device__ float g_vt  [HEADS * NFULL * CDIM];  // vtT hi/lo bf16 pairs
__device__ float g_wt  [CDIM * 2 * CDIM / 2];

__device__ __constant__ float KQ = (float)(0.25 * 3.14159265358979323846 * (1.0 - 1e-7));

__device__ __forceinline__ float gelu_f(float x) {
    float x3 = x * x * x;
    return 0.5f * x * (1.0f + tanhf(0.7978845608028654f * (x + 0.044715f * x3)));
}

__device__ __forceinline__ void split_f(float f, __nv_bfloat16& hi, __nv_bfloat16& lo) {
    hi = __float2bfloat16(f);
    lo = __float2bfloat16(f - __bfloat162float(hi));
}

__device__ __forceinline__ uint32_t smem_u32(const void* p) {
    uint32_t a;
    asm("{ .reg .u64 t; cvta.to.shared.u64 t, %1; cvt.u32.u64 %0, t; }" : "=r"(a) : "l"(p));
    return a;
}

__device__ __forceinline__ void ldsm_x4(uint32_t* d, uint32_t addr) {
    asm volatile("ldmatrix.sync.aligned.m8n8.x4.shared.b16 {%0,%1,%2,%3}, [%4];"
                 : "=r"(d[0]), "=r"(d[1]), "=r"(d[2]), "=r"(d[3]) : "r"(addr));
}

__device__ __forceinline__ void mma16816(float* c, const uint32_t* a, uint32_t b0, uint32_t b1) {
    asm volatile("mma.sync.aligned.m16n8k16.row.col.f32.bf16.bf16.f32 "
                 "{%0,%1,%2,%3}, {%4,%5,%6,%7}, {%8,%9}, {%0,%1,%2,%3};"
                 : "+f"(c[0]), "+f"(c[1]), "+f"(c[2]), "+f"(c[3])
                 : "r"(a[0]), "r"(a[1]), "r"(a[2]), "r"(a[3]), "r"(b0), "r"(b1));
}

__device__ __forceinline__ void cp16(uint32_t dst, const void* src) {
    asm volatile("cp.async.cg.shared.global [%0], [%1], 16;" :: "r"(dst), "l"(src));
}
#define CP_COMMIT() asm volatile("cp.async.commit_group;" ::: "memory")
#define CP_WAIT1()  asm volatile("cp.async.wait_group 1;" ::: "memory")

// ---------------- encoder ----------------
__global__ void encoder_k(const float* __restrict__ x, const float* __restrict__ w,
                          const float* __restrict__ b, __nv_bfloat16* __restrict__ out) {
    long row = blockIdx.x;
    int c = threadIdx.x;
    const float* xr = x + row * 4;
    float acc = b[c] + xr[0] * w[c] + xr[1] * w[256 + c]
                     + xr[2] * w[512 + c] + xr[3] * w[768 + c];
    float g = gelu_f(acc);
    __nv_bfloat16 hi, lo; split_f(g, hi, lo);
    out[row * 512 + c] = hi;
    out[row * 512 + 256 + c] = lo;
}

// ---------------- weight conversions ----------------
__global__ void cvt_wT_k(const float* __restrict__ w, __nv_bfloat16* __restrict__ o) {
    int n = blockIdx.x, k = threadIdx.x;
    float v = w[k * 256 + n];
    __nv_bfloat16 hi, lo; split_f(v, hi, lo);
    o[n * 512 + k] = hi;
    o[n * 512 + 256 + k] = lo;
}
__global__ void cvt_w2_k(const float* __restrict__ w, __nv_bfloat16* __restrict__ o) {
    int c = blockIdx.x, j = threadIdx.x;
    int h = c >> 5, vd = c & 31;
    float v = w[(h * 256 + j) * 32 + vd];
    __nv_bfloat16 hi, lo; split_f(v, hi, lo);
    o[c * 512 + j] = hi;
    o[c * 512 + 256 + j] = lo;
}

// ---------------- unmasked softmax -> hi/lo att rows of stride 2L ----------------
template <int L>
__global__ void __launch_bounds__(256) softmax_k(const float* __restrict__ md,
                                                 const float* __restrict__ r,
                                                 __nv_bfloat16* __restrict__ att, int Nq) {
    const int E = L / 256;
    __shared__ float red[256];
    long row = blockIdx.x;
    int h = (int)(row / Nq);
    float scale = tanf(KQ * (1.0f + sinf(r[h])));
    const float* src = md + row * (long)L;
    int tid = threadIdx.x;
    float v[E];
    float mn = 3.4e38f;
    #pragma unroll
    for (int e = 0; e < E; e++) { v[e] = src[tid + 256 * e] * scale; mn = fminf(mn, v[e]); }
    red[tid] = mn; __syncthreads();
    for (int o = 128; o > 0; o >>= 1) { if (tid < o) red[tid] = fminf(red[tid], red[tid + o]); __syncthreads(); }
    mn = red[0]; __syncthreads();
    float s = 0.0f;
    #pragma unroll
    for (int e = 0; e < E; e++) { v[e] = expf(mn - v[e]); s += v[e]; }
    red[tid] = s; __syncthreads();
    for (int o = 128; o > 0; o >>= 1) { if (tid < o) red[tid] += red[tid + o]; __syncthreads(); }
    float inv = 1.0f / red[0];
    long rb = row * (long)(2 * L);
    #pragma unroll
    for (int e = 0; e < E; e++) {
        float f = v[e] * inv;
        __nv_bfloat16 hi, lo; split_f(f, hi, lo);
        att[rb + tid + 256 * e] = hi;
        att[rb + L + tid + 256 * e] = lo;
    }
}

// ---------------- percentile-masked softmax (P_LOC=30, L=1024) -> hi/lo ----------------
__global__ void __launch_bounds__(256) pct_att_k(const float* __restrict__ md,
                                                 const float* __restrict__ r,
                                                 __nv_bfloat16* __restrict__ att) {
    const int L = 1024;
    typedef cub::BlockRadixSort<float, 256, 4> Sort;
    __shared__ typename Sort::TempStorage sort_tmp;
    __shared__ float orig[L];
    __shared__ float red[256];
    __shared__ float sh_thr, sh_min;
    int row = blockIdx.x;
    int h = row >> 10;
    float scale = tanf(KQ * (1.0f + sinf(r[h])));
    int tid = threadIdx.x;
    const float* src = md + (long)row * L;
    float items[4];
    #pragma unroll
    for (int i = 0; i < 4; i++) {
        float v = src[tid * 4 + i] * scale;
        items[i] = v; orig[tid * 4 + i] = v;
    }
    __syncthreads();
    Sort(sort_tmp).Sort(items);
    if (tid == 76) sh_thr = items[2];       // sorted[306]
    if (tid == 0)  sh_min = items[0];
    __syncthreads();
    float thr = sh_thr, mn = sh_min;
    float vals[4]; float s = 0.0f;
    #pragma unroll
    for (int i = 0; i < 4; i++) {
        float v = orig[tid * 4 + i];
        float e = (v <= thr) ? expf(mn - v) : 0.0f;
        vals[i] = e; s += e;
    }
    red[tid] = s; __syncthreads();
    for (int o = 128; o > 0; o >>= 1) { if (tid < o) red[tid] += red[tid + o]; __syncthreads(); }
    float inv = 1.0f / red[0];
    long rb = (long)row * 2048;
    #pragma unroll
    for (int i = 0; i < 4; i++) {
        float f = vals[i] * inv;
        __nv_bfloat16 hi, lo; split_f(f, hi, lo);
        att[rb + tid * 4 + i] = hi;
        att[rb + 1024 + tid * 4 + i] = lo;
    }
}

// ---------------- cp.async pipelined mma.sync GEMM (hi/lo 3-term) ----------------
// C[m][n] = sum_k A[m][k]*B[n][k]. Tile 128(M)x64(N), 8 warps (4m x 2n), warp 32x32.
// K-chunk 64 (one barrier per 32 MMAs/warp), 3-stage cp.async pipeline, RPAD=144.
// 3 sequential term passes over K: (Ahi,Bhi), (Ahi,Blo), (Alo,Bhi).
// MODE 0: vt scatter; 1: att-out gelu scatter; 2: gelu+bias->hi/lo;
// MODE 3: bias->fp32; 4: gelu+bias+other->hi/lo; 5: gelu+bias->fp32
#define RPAD 144
#define STAGES 3
#define A_BYTES (128 * RPAD)
#define B_BYTES (64 * RPAD)
#define STAGE_BYTES (A_BYTES + B_BYTES)
#define SMEM_DYN (STAGES * STAGE_BYTES)

template <int MODE>
__global__ void __launch_bounds__(256) mma_k(const __nv_bfloat16* __restrict__ Aab,
                                             const __nv_bfloat16* __restrict__ Bab,
                                             void* __restrict__ Cout,
                                             const float* __restrict__ bias,
                                             const float* __restrict__ other,
                                             int M, int K, long sAz, long sBz, int Nn) {
    extern __shared__ __align__(16) char smem[];
    uint32_t sa = smem_u32(smem);
    int tid = threadIdx.x, wid = tid >> 5, lane = tid & 31;
    int wm = wid & 3, wn = wid >> 2;
    int m0 = blockIdx.y * 128, n0 = blockIdx.x * 64;
    long rstride = 2L * K;

    const __nv_bfloat16* Ag = Aab + blockIdx.z * sAz;
    const __nv_bfloat16* Bg = Bab + blockIdx.z * sBz;

    const int KC = K >> 6;         // 64-elt chunks per term
    const int NI = 3 * KC;

    // cp.async roles:
    // A: 128 rows x 128B -> row=tid>>1, half=(tid&1) covers 64B = 4 cp16
    // B: 64 rows x 128B  -> row=tid>>2, quarter=(tid&3) covers 32B = 2 cp16
    int ar = tid >> 1, ah = tid & 1;
    int br = tid >> 2, bq = tid & 3;
    const __nv_bfloat16* AsrcR = Ag + (long)(m0 + ar) * rstride + ah * 32;
    const __nv_bfloat16* BsrcR = Bg + (long)(n0 + br) * rstride + bq * 16;
    uint32_t daA = (uint32_t)(ar * RPAD + ah * 64);
    uint32_t daB = (uint32_t)(br * RPAD + bq * 32);

    float acc[2][4][4];
    #pragma unroll
    for (int i = 0; i < 2; i++)
        #pragma unroll
        for (int j = 0; j < 4; j++)
            #pragma unroll
            for (int e = 0; e < 4; e++) acc[i][j][e] = 0.0f;

    // ldmatrix lane offsets
    int q = lane >> 3, rr = lane & 7;
    uint32_t a_row_off = (uint32_t)((wm * 32 + ((q & 1) * 8) + rr) * RPAD + (q >> 1) * 16);
    uint32_t b_row_off = (uint32_t)((wn * 32 + ((q >> 1) * 8) + rr) * RPAD + (q & 1) * 16);

    // prologue: fill STAGES-1 chunks
    #pragma unroll
    for (int s = 0; s < STAGES - 1; s++) {
        int t = (s >= KC) + (s >= 2 * KC);
        int kc = s - t * KC;
        long ao = (long)((t == 2) ? K : 0) + (long)kc * 64;
        long bo = (long)((t == 1) ? K : 0) + (long)kc * 64;
        uint32_t ab = sa + s * STAGE_BYTES;
        const __nv_bfloat16* asrc = AsrcR + ao;
        #pragma unroll
        for (int i = 0; i < 4; i++) cp16(ab + daA + i * 16, asrc + i * 8);
        const __nv_bfloat16* bsrc = BsrcR + bo;
        #pragma unroll
        for (int i = 0; i < 2; i++) cp16(ab + A_BYTES + daB + i * 16, bsrc + i * 8);
        CP_COMMIT();
    }

    for (int ii = 0; ii < NI; ii++) {
        CP_WAIT1();
        __syncthreads();

        int nx = ii + STAGES - 1;
        if (nx < NI) {
            int t = (nx >= KC) + (nx >= 2 * KC);
            int kc = nx - t * KC;
            long ao = (long)((t == 2) ? K : 0) + (long)kc * 64;
            long bo = (long)((t == 1) ? K : 0) + (long)kc * 64;
            uint32_t ab = sa + ((nx >= STAGES) ? (nx - STAGES * (nx / STAGES)) : nx) * STAGE_BYTES;
            // nx % 3 without div is messy; NI small so keep mod of small int:
            ab = sa + (nx % STAGES) * STAGE_BYTES;
            const __nv_bfloat16* asrc = AsrcR + ao;
            #pragma unroll
            for (int i = 0; i < 4; i++) cp16(ab + daA + i * 16, asrc + i * 8);
            const __nv_bfloat16* bsrc = BsrcR + bo;
            #pragma unroll
            for (int i = 0; i < 2; i++) cp16(ab + A_BYTES + daB + i * 16, bsrc + i * 8);
        }
        CP_COMMIT();

        uint32_t a_sm = sa + (ii % STAGES) * STAGE_BYTES;
        uint32_t b_sm = a_sm + A_BYTES;

        // software-pipelined fragments over 4 k16 steps
        uint32_t af[2][2][4], bf[2][2][4];
        ldsm_x4(af[0][0], a_sm + a_row_off);
        ldsm_x4(af[0][1], a_sm + a_row_off + 16 * RPAD);
        ldsm_x4(bf[0][0], b_sm + b_row_off);
        ldsm_x4(bf[0][1], b_sm + b_row_off + 16 * RPAD);
        #pragma unroll
        for (int kk = 0; kk < 4; kk++) {
            int cur = kk & 1, nxt = cur ^ 1;
            if (kk < 3) {
                uint32_t ko = (uint32_t)((kk + 1) * 32);
                ldsm_x4(af[nxt][0], a_sm + a_row_off + ko);
                ldsm_x4(af[nxt][1], a_sm + a_row_off + 16 * RPAD + ko);
                ldsm_x4(bf[nxt][0], b_sm + b_row_off + ko);
                ldsm_x4(bf[nxt][1], b_sm + b_row_off + 16 * RPAD + ko);
            }
            #pragma unroll
            for (int i = 0; i < 2; i++)
                #pragma unroll
                for (int j = 0; j < 4; j++)
                    mma16816(acc[i][j], af[cur][i],
                             bf[cur][j >> 1][(j & 1) * 2], bf[cur][j >> 1][(j & 1) * 2 + 1]);
        }
    }

    // epilogue: frag (i,j): rows m0+wm*32+i*16+(lane>>2)+{0,8}, cols n0+wn*32+j*8+(lane&3)*2+{0,1}
    #pragma unroll
    for (int i = 0; i < 2; i++) {
        #pragma unroll
        for (int j = 0; j < 4; j++) {
            #pragma unroll
            for (int hh = 0; hh < 2; hh++) {
                int m = m0 + wm * 32 + i * 16 + (lane >> 2) + hh * 8;
                int cg = n0 + wn * 32 + j * 8 + (lane & 3) * 2;
                #pragma unroll
                for (int e = 0; e < 2; e++) {
                    float v = acc[i][j][hh * 2 + e];
                    int c = cg + e;
                    if (MODE == 0) {
                        int head = m >> 5, vd = m & 31;
                        int bb = c / Nn, nn = c - bb * Nn;
                        long base = ((long)head * 256 + (bb << 5) + vd) * (2L * Nn);
                        __nv_bfloat16 hi, lo; split_f(v, hi, lo);
                        ((__nv_bfloat16*)Cout)[base + nn] = hi;
                        ((__nv_bfloat16*)Cout)[base + Nn + nn] = lo;
                    } else if (MODE == 1) {
                        float gl = gelu_f(v);
                        int bb = c >> 5, vd = c & 31;
                        long a = ((long)bb * M + m) * 512 + blockIdx.z * 32 + vd;
                        __nv_bfloat16 hi, lo; split_f(gl, hi, lo);
                        ((__nv_bfloat16*)Cout)[a] = hi;
                        ((__nv_bfloat16*)Cout)[a + 256] = lo;
                    } else if (MODE == 2) {
                        float gl = gelu_f(v + bias[c]);
                        __nv_bfloat16 hi, lo; split_f(gl, hi, lo);
                        ((__nv_bfloat16*)Cout)[(long)m * 512 + c] = hi;
                        ((__nv_bfloat16*)Cout)[(long)m * 512 + 256 + c] = lo;
                    } else if (MODE == 3) {
                        ((float*)Cout)[(long)m * 256 + c] = v + bias[c];
                    } else if (MODE == 4) {
                        float gl = gelu_f(v + bias[c] + other[(long)m * 256 + c]);
                        __nv_bfloat16 hi, lo; split_f(gl, hi, lo);
                        ((__nv_bfloat16*)Cout)[(long)m * 512 + c] = hi;
                        ((__nv_bfloat16*)Cout)[(long)m * 512 + 256 + c] = lo;
                    } else {
                        ((float*)Cout)[(long)m * 256 + c] = gelu_f(v + bias[c]);
                    }
                }
            }
        }
    }
}

// ---------------- final projection ----------------
__global__ void final_k(const float* __restrict__ h, const float* __restrict__ w,
                        const float* __restrict__ b, float* __restrict__ out) {
    int row = blockIdx.x * 8 + (threadIdx.x >> 5);
    int lane = threadIdx.x & 31;
    const float* hr = h + (long)row * CDIM;
    float acc = 0.0f;
    #pragma unroll
    for (int c = lane; c < CDIM; c += 32) acc += hr[c] * w[c];
    #pragma unroll
    for (int o = 16; o > 0; o >>= 1) acc += __shfl_down_sync(0xffffffffu, acc, o);
    if (lane == 0) out[row] = acc + b[0];
}

// ---------------- host orchestration ----------------
static float* sym(const void* s) {
    void* p = nullptr;
    cudaGetSymbolAddress(&p, s);
    return (float*)p;
}

extern "C" void kernel_launch(void* const* d_in, const int* in_sizes, int n_in,
                              void* d_out, int out_size) {
    const float* x         = (const float*)d_in[0];
    const float* m_down    = (const float*)d_in[1];
    const float* m_p0      = (const float*)d_in[2];
    const float* m_p1      = (const float*)d_in[3];
    const float* m_up      = (const float*)d_in[4];
    const float* en_w      = (const float*)d_in[5];
    const float* en_b      = (const float*)d_in[6];
    const float* down_r    = (const float*)d_in[7];
    const float* down_w    = (const float*)d_in[8];
    const float* pa_r[2]   = {(const float*)d_in[9],  (const float*)d_in[17]};
    const float* pa_w[2]   = {(const float*)d_in[10], (const float*)d_in[18]};
    const float* f1w[2]    = {(const float*)d_in[11], (const float*)d_in[19]};
    const float* f1b[2]    = {(const float*)d_in[12], (const float*)d_in[20]};
    const float* f2w[2]    = {(const float*)d_in[13], (const float*)d_in[21]};
    const float* f2b[2]    = {(const float*)d_in[14], (const float*)d_in[22]};
    const float* rw[2]     = {(const float*)d_in[15], (const float*)d_in[23]};
    const float* rb[2]     = {(const float*)d_in[16], (const float*)d_in[24]};
    const float* up_r      = (const float*)d_in[25];
    const float* up_w      = (const float*)d_in[26];
    const float* de1w      = (const float*)d_in[27];
    const float* de1b      = (const float*)d_in[28];
    const float* de2w      = (const float*)d_in[29];
    const float* de2b      = (const float*)d_in[30];
    const float* mdp[2]    = {m_p0, m_p1};

    __nv_bfloat16* h0  = (__nv_bfloat16*)sym(g_bufA);
    float*         de1 = sym(g_bufB);
    __nv_bfloat16* Lb[3] = {(__nv_bfloat16*)sym(g_bufL0), (__nv_bfloat16*)sym(g_bufL1),
                            (__nv_bfloat16*)sym(g_bufL2)};
    float*         mlp32 = sym(g_mlp);
    __nv_bfloat16* att = (__nv_bfloat16*)sym(g_att);
    __nv_bfloat16* vtT = (__nv_bfloat16*)sym(g_vt);
    __nv_bfloat16* wt  = (__nv_bfloat16*)sym(g_wt);

    static bool attr_set = false;
    if (!attr_set) {
        cudaFuncSetAttribute(mma_k<0>, cudaFuncAttributeMaxDynamicSharedMemorySize, SMEM_DYN);
        cudaFuncSetAttribute(mma_k<1>, cudaFuncAttributeMaxDynamicSharedMemorySize, SMEM_DYN);
        cudaFuncSetAttribute(mma_k<2>, cudaFuncAttributeMaxDynamicSharedMemorySize, SMEM_DYN);
        cudaFuncSetAttribute(mma_k<3>, cudaFuncAttributeMaxDynamicSharedMemorySize, SMEM_DYN);
        cudaFuncSetAttribute(mma_k<4>, cudaFuncAttributeMaxDynamicSharedMemorySize, SMEM_DYN);
        cudaFuncSetAttribute(mma_k<5>, cudaFuncAttributeMaxDynamicSharedMemorySize, SMEM_DYN);
        attr_set = true;
    }

    // 1. encoder -> h0 hi/lo [B*4096, 512]
    encoder_k<<<B_SZ * NFULL, 256>>>(x, en_w, en_b, h0);

    // 2. down attention
    softmax_k<NFULL><<<HEADS * NLAT, 256>>>(m_down, down_r, att, NLAT);
    cvt_w2_k<<<256, 256>>>(down_w, wt);
    // vtT (A = w2 [256 rows], B = h0 [32768 rows], K = 256)
    mma_k<0><<<dim3(512, 2, 1), 256, SMEM_DYN>>>(wt, h0, vtT, nullptr, nullptr,
                                                 256, 256, 0, 0, NFULL);
    // att@vt per head -> L0 hi/lo
    mma_k<1><<<dim3(4, 8, 8), 256, SMEM_DYN>>>(att, vtT, Lb[0], nullptr, nullptr,
                                               NLAT, NFULL, (long)NLAT * 2 * NFULL,
                                               (long)256 * 2 * NFULL, 0);

    // 3. two latent blocks
    __nv_bfloat16* hcur = Lb[0];
    __nv_bfloat16* s0 = Lb[1];
    __nv_bfloat16* s1 = Lb[2];
    for (int blk = 0; blk < 2; blk++) {
        pct_att_k<<<HEADS * NLAT, 256>>>(mdp[blk], pa_r[blk], att);
        cvt_w2_k<<<256, 256>>>(pa_w[blk], wt);
        mma_k<0><<<dim3(128, 2, 1), 256, SMEM_DYN>>>(wt, hcur, vtT, nullptr, nullptr,
                                                     256, 256, 0, 0, NLAT);
        mma_k<1><<<dim3(4, 8, 8), 256, SMEM_DYN>>>(att, vtT, s0, nullptr, nullptr,
                                                   NLAT, NLAT, (long)NLAT * 2 * NLAT,
                                                   (long)256 * 2 * NLAT, 0);
        cvt_wT_k<<<256, 256>>>(f1w[blk], wt);
        mma_k<2><<<dim3(4, 64, 1), 256, SMEM_DYN>>>(s0, wt, s1, f1b[blk], nullptr,
                                                    B_SZ * NLAT, 256, 0, 0, 0);
        cvt_wT_k<<<256, 256>>>(f2w[blk], wt);
        mma_k<3><<<dim3(4, 64, 1), 256, SMEM_DYN>>>(s1, wt, mlp32, f2b[blk], nullptr,
                                                    B_SZ * NLAT, 256, 0, 0, 0);
        cvt_wT_k<<<256, 256>>>(rw[blk], wt);
        mma_k<4><<<dim3(4, 64, 1), 256, SMEM_DYN>>>(hcur, wt, s0, rb[blk], mlp32,
                                                    B_SZ * NLAT, 256, 0, 0, 0);
        __nv_bfloat16* tmp = hcur; hcur = s0; s0 = tmp;
    }

    // 4. up attention -> h0 hi/lo [B*4096, 512]
    softmax_k<NLAT><<<HEADS * NFULL, 256>>>(m_up, up_r, att, NFULL);
    cvt_w2_k<<<256, 256>>>(up_w, wt);
    mma_k<0><<<dim3(128, 2, 1), 256, SMEM_DYN>>>(wt, hcur, vtT, nullptr, nullptr,
                                                 256, 256, 0, 0, NLAT);
    mma_k<1><<<dim3(4, 32, 8), 256, SMEM_DYN>>>(att, vtT, h0, nullptr, nullptr,
                                                NFULL, NLAT, (long)NFULL * 2 * NLAT,
                                                (long)256 * 2 * NLAT, 0);

    // 5. decoder
    cvt_wT_k<<<256, 256>>>(de1w, wt);
    mma_k<5><<<dim3(4, 256, 1), 256, SMEM_DYN>>>(h0, wt, de1, de1b, nullptr,
                                                 B_SZ * NFULL, 256, 0, 0, 0);
    final_k<<<(B_SZ * NFULL) / 8, 256>>>(de1, de2w, de2b, (float*)d_out);
}

// round 12
// speedup vs baseline: 1.2130x; 1.2130x over previous
#include <cuda_runtime.h>
#include <cuda_bf16.h>
#include <cub/block/block_radix_sort.cuh>
#include <cstdint>

#define B_SZ   8
#define NFULL  4096
#define NLAT   1024
#define CDIM   256
#define HEADS  8
#define VDIM   32

// ---------------- scratch (static device arrays; no allocation) ----------------
__device__ float g_bufA[B_SZ * NFULL * CDIM];   // h0 hi/lo (bf16 pairs), later up-att out
__device__ float g_bufB[B_SZ * NFULL * CDIM];   // de1 out fp32
__device__ float g_bufL0[B_SZ * NLAT * CDIM];
__device__ float g_bufL1[B_SZ * NLAT * CDIM];
__device__ float g_bufL2[B_SZ * NLAT * CDIM];
__device__ float g_mlp [B_SZ * NLAT * CDIM];
__device__ float g_attD [HEADS * NLAT * NFULL]; // down att hi/lo bf16 pairs
__device__ float g_attU [HEADS * NFULL * NLAT]; // up att hi/lo bf16 pairs
__device__ float g_attP0[HEADS * NLAT * NLAT];  // latent att hi/lo
__device__ float g_attP1[HEADS * NLAT * NLAT];
__device__ float g_vt  [HEADS * NFULL * CDIM];  // vtT hi/lo bf16 pairs
__device__ float g_wt  [CDIM * 2 * CDIM / 2];

__device__ __constant__ float KQ = (float)(0.25 * 3.14159265358979323846 * (1.0 - 1e-7));

__device__ __forceinline__ float gelu_f(float x) {
    float x3 = x * x * x;
    return 0.5f * x * (1.0f + tanhf(0.7978845608028654f * (x + 0.044715f * x3)));
}

__device__ __forceinline__ void split_f(float f, __nv_bfloat16& hi, __nv_bfloat16& lo) {
    hi = __float2bfloat16(f);
    lo = __float2bfloat16(f - __bfloat162float(hi));
}

__device__ __forceinline__ uint32_t smem_u32(const void* p) {
    uint32_t a;
    asm("{ .reg .u64 t; cvta.to.shared.u64 t, %1; cvt.u32.u64 %0, t; }" : "=r"(a) : "l"(p));
    return a;
}

__device__ __forceinline__ void ldsm_x4(uint32_t* d, uint32_t addr) {
    asm volatile("ldmatrix.sync.aligned.m8n8.x4.shared.b16 {%0,%1,%2,%3}, [%4];"
                 : "=r"(d[0]), "=r"(d[1]), "=r"(d[2]), "=r"(d[3]) : "r"(addr));
}

__device__ __forceinline__ void mma16816(float* c, const uint32_t* a, uint32_t b0, uint32_t b1) {
    asm volatile("mma.sync.aligned.m16n8k16.row.col.f32.bf16.bf16.f32 "
                 "{%0,%1,%2,%3}, {%4,%5,%6,%7}, {%8,%9}, {%0,%1,%2,%3};"
                 : "+f"(c[0]), "+f"(c[1]), "+f"(c[2]), "+f"(c[3])
                 : "r"(a[0]), "r"(a[1]), "r"(a[2]), "r"(a[3]), "r"(b0), "r"(b1));
}

__device__ __forceinline__ void cp16(uint32_t dst, const void* src) {
    asm volatile("cp.async.cg.shared.global [%0], [%1], 16;" :: "r"(dst), "l"(src));
}
#define CP_COMMIT() asm volatile("cp.async.commit_group;" ::: "memory")
#define CP_WAIT2()  asm volatile("cp.async.wait_group 2;" ::: "memory")

// ---------------- encoder ----------------
__global__ void encoder_k(const float* __restrict__ x, const float* __restrict__ w,
                          const float* __restrict__ b, __nv_bfloat16* __restrict__ out) {
    long row = blockIdx.x;
    int c = threadIdx.x;
    const float* xr = x + row * 4;
    float acc = b[c] + xr[0] * w[c] + xr[1] * w[256 + c]
                     + xr[2] * w[512 + c] + xr[3] * w[768 + c];
    float g = gelu_f(acc);
    __nv_bfloat16 hi, lo; split_f(g, hi, lo);
    out[row * 512 + c] = hi;
    out[row * 512 + 256 + c] = lo;
}

// ---------------- weight conversions ----------------
__global__ void cvt_wT_k(const float* __restrict__ w, __nv_bfloat16* __restrict__ o) {
    int n = blockIdx.x, k = threadIdx.x;
    float v = w[k * 256 + n];
    __nv_bfloat16 hi, lo; split_f(v, hi, lo);
    o[n * 512 + k] = hi;
    o[n * 512 + 256 + k] = lo;
}
__global__ void cvt_w2_k(const float* __restrict__ w, __nv_bfloat16* __restrict__ o) {
    int c = blockIdx.x, j = threadIdx.x;
    int h = c >> 5, vd = c & 31;
    float v = w[(h * 256 + j) * 32 + vd];
    __nv_bfloat16 hi, lo; split_f(v, hi, lo);
    o[c * 512 + j] = hi;
    o[c * 512 + 256 + j] = lo;
}

// ---------------- unmasked softmax -> hi/lo att rows of stride 2L ----------------
template <int L>
__global__ void __launch_bounds__(256) softmax_k(const float* __restrict__ md,
                                                 const float* __restrict__ r,
                                                 __nv_bfloat16* __restrict__ att, int Nq) {
    const int E = L / 256;
    __shared__ float red[256];
    long row = blockIdx.x;
    int h = (int)(row / Nq);
    float scale = tanf(KQ * (1.0f + sinf(r[h])));
    const float* src = md + row * (long)L;
    int tid = threadIdx.x;
    float v[E];
    float mn = 3.4e38f;
    #pragma unroll
    for (int e = 0; e < E; e++) { v[e] = src[tid + 256 * e] * scale; mn = fminf(mn, v[e]); }
    red[tid] = mn; __syncthreads();
    for (int o = 128; o > 0; o >>= 1) { if (tid < o) red[tid] = fminf(red[tid], red[tid + o]); __syncthreads(); }
    mn = red[0]; __syncthreads();
    float s = 0.0f;
    #pragma unroll
    for (int e = 0; e < E; e++) { v[e] = __expf(mn - v[e]); s += v[e]; }
    red[tid] = s; __syncthreads();
    for (int o = 128; o > 0; o >>= 1) { if (tid < o) red[tid] += red[tid + o]; __syncthreads(); }
    float inv = 1.0f / red[0];
    long rb = row * (long)(2 * L);
    #pragma unroll
    for (int e = 0; e < E; e++) {
        float f = v[e] * inv;
        __nv_bfloat16 hi, lo; split_f(f, hi, lo);
        att[rb + tid + 256 * e] = hi;
        att[rb + L + tid + 256 * e] = lo;
    }
}

// ---------------- percentile-masked softmax (P_LOC=30, L=1024) -> hi/lo ----------------
__global__ void __launch_bounds__(256) pct_att_k(const float* __restrict__ md,
                                                 const float* __restrict__ r,
                                                 __nv_bfloat16* __restrict__ att) {
    const int L = 1024;
    typedef cub::BlockRadixSort<float, 256, 4> Sort;
    __shared__ typename Sort::TempStorage sort_tmp;
    __shared__ float orig[L];
    __shared__ float red[256];
    __shared__ float sh_thr, sh_min;
    int row = blockIdx.x;
    int h = row >> 10;
    float scale = tanf(KQ * (1.0f + sinf(r[h])));
    int tid = threadIdx.x;
    const float* src = md + (long)row * L;
    float items[4];
    #pragma unroll
    for (int i = 0; i < 4; i++) {
        float v = src[tid * 4 + i] * scale;
        items[i] = v; orig[tid * 4 + i] = v;
    }
    __syncthreads();
    Sort(sort_tmp).Sort(items);
    if (tid == 76) sh_thr = items[2];       // sorted[306]
    if (tid == 0)  sh_min = items[0];
    __syncthreads();
    float thr = sh_thr, mn = sh_min;
    float vals[4]; float s = 0.0f;
    #pragma unroll
    for (int i = 0; i < 4; i++) {
        float v = orig[tid * 4 + i];
        float e = (v <= thr) ? __expf(mn - v) : 0.0f;
        vals[i] = e; s += e;
    }
    red[tid] = s; __syncthreads();
    for (int o = 128; o > 0; o >>= 1) { if (tid < o) red[tid] += red[tid + o]; __syncthreads(); }
    float inv = 1.0f / red[0];
    long rb = (long)row * 2048;
    #pragma unroll
    for (int i = 0; i < 4; i++) {
        float f = vals[i] * inv;
        __nv_bfloat16 hi, lo; split_f(f, hi, lo);
        att[rb + tid * 4 + i] = hi;
        att[rb + 1024 + tid * 4 + i] = lo;
    }
}

// ---------------- cp.async pipelined mma.sync GEMM (hi/lo 3-term) — R5 config -----
// C[m][n] = sum_k A[m][k]*B[n][k]. Tile 128(M)x64(N), 8 warps (4m x 2n), warp 32x32.
// K-chunk 32, 4-stage cp.async pipeline. Rows padded to RPAD=80 B.
// MODE 0: vt scatter; 1: att-out gelu scatter; 2: gelu+bias->hi/lo;
// MODE 3: bias->fp32; 4: gelu+bias+other->hi/lo; 5: gelu+bias->fp32
#define RPAD 80
#define STAGES 4
#define A_BYTES (128 * RPAD)
#define B_BYTES (64 * RPAD)
#define STAGE_BYTES (A_BYTES + B_BYTES)
#define SMEM_DYN (STAGES * STAGE_BYTES)

template <int MODE>
__global__ void __launch_bounds__(256) mma_k(const __nv_bfloat16* __restrict__ Aab,
                                             const __nv_bfloat16* __restrict__ Bab,
                                             void* __restrict__ Cout,
                                             const float* __restrict__ bias,
                                             const float* __restrict__ other,
                                             int M, int K, long sAz, long sBz, int Nn) {
    extern __shared__ __align__(16) char smem[];
    uint32_t sa = smem_u32(smem);
    int tid = threadIdx.x, wid = tid >> 5, lane = tid & 31;
    int wm = wid & 3, wn = wid >> 2;
    int m0 = blockIdx.y * 128, n0 = blockIdx.x * 64;
    long rstride = 2L * K;

    const __nv_bfloat16* Ag = Aab + blockIdx.z * sAz;
    const __nv_bfloat16* Bg = Bab + blockIdx.z * sBz;

    const int KC = K >> 5;
    const int NI = 3 * KC;

    // cp.async roles: thread -> (row = tid>>2 [+64 for A], 16B-seg = tid&3)
    int r0 = tid >> 2, seg = tid & 3;
    const __nv_bfloat16* Asrc0 = Ag + (long)(m0 + r0) * rstride + seg * 8;
    const __nv_bfloat16* Asrc1 = Asrc0 + 64 * rstride;
    const __nv_bfloat16* Bsrc0 = Bg + (long)(n0 + r0) * rstride + seg * 8;
    uint32_t da = (uint32_t)(r0 * RPAD + seg * 16);

    float acc[2][4][4];
    #pragma unroll
    for (int i = 0; i < 2; i++)
        #pragma unroll
        for (int j = 0; j < 4; j++)
            #pragma unroll
            for (int e = 0; e < 4; e++) acc[i][j][e] = 0.0f;

    // ldmatrix lane offsets
    int q = lane >> 3, rr = lane & 7;
    uint32_t a_row_off = (uint32_t)((wm * 32 + ((q & 1) * 8) + rr) * RPAD + (q >> 1) * 16);
    uint32_t b_row_off = (uint32_t)((wn * 32 + ((q >> 1) * 8) + rr) * RPAD + (q & 1) * 16);

    // prologue: fill STAGES-1 chunks
    #pragma unroll
    for (int s = 0; s < STAGES - 1; s++) {
        int term = s / KC, kc = s - term * KC;
        long ao = (long)((term == 2) ? K : 0) + (long)kc * 32;
        long bo = (long)((term == 1) ? K : 0) + (long)kc * 32;
        uint32_t ab = sa + s * STAGE_BYTES;
        cp16(ab + da, Asrc0 + ao);
        cp16(ab + da + 64 * RPAD, Asrc1 + ao);
        cp16(ab + A_BYTES + da, Bsrc0 + bo);
        CP_COMMIT();
    }

    for (int ii = 0; ii < NI; ii++) {
        CP_WAIT2();
        __syncthreads();

        int nx = ii + STAGES - 1;
        if (nx < NI) {
            int term = nx / KC, kc = nx - term * KC;
            long ao = (long)((term == 2) ? K : 0) + (long)kc * 32;
            long bo = (long)((term == 1) ? K : 0) + (long)kc * 32;
            uint32_t ab = sa + (nx % STAGES) * STAGE_BYTES;
            cp16(ab + da, Asrc0 + ao);
            cp16(ab + da + 64 * RPAD, Asrc1 + ao);
            cp16(ab + A_BYTES + da, Bsrc0 + bo);
        }
        CP_COMMIT();

        uint32_t a_sm = sa + (ii % STAGES) * STAGE_BYTES;
        uint32_t b_sm = a_sm + A_BYTES;
        #pragma unroll
        for (int kk = 0; kk < 2; kk++) {
            uint32_t af[2][4];
            ldsm_x4(af[0], a_sm + a_row_off + kk * 32);
            ldsm_x4(af[1], a_sm + a_row_off + 16 * RPAD + kk * 32);
            uint32_t bf[2][4];
            ldsm_x4(bf[0], b_sm + b_row_off + kk * 32);
            ldsm_x4(bf[1], b_sm + b_row_off + 16 * RPAD + kk * 32);
            #pragma unroll
            for (int i = 0; i < 2; i++)
                #pragma unroll
                for (int j = 0; j < 4; j++)
                    mma16816(acc[i][j], af[i], bf[j >> 1][(j & 1) * 2], bf[j >> 1][(j & 1) * 2 + 1]);
        }
    }

    // epilogue
    #pragma unroll
    for (int i = 0; i < 2; i++) {
        #pragma unroll
        for (int j = 0; j < 4; j++) {
            #pragma unroll
            for (int hh = 0; hh < 2; hh++) {
                int m = m0 + wm * 32 + i * 16 + (lane >> 2) + hh * 8;
                int cg = n0 + wn * 32 + j * 8 + (lane & 3) * 2;
                #pragma unroll
                for (int e = 0; e < 2; e++) {
                    float v = acc[i][j][hh * 2 + e];
                    int c = cg + e;
                    if (MODE == 0) {
                        int head = m >> 5, vd = m & 31;
                        int bb = c / Nn, nn = c - bb * Nn;
                        long base = ((long)head * 256 + (bb << 5) + vd) * (2L * Nn);
                        __nv_bfloat16 hi, lo; split_f(v, hi, lo);
                        ((__nv_bfloat16*)Cout)[base + nn] = hi;
                        ((__nv_bfloat16*)Cout)[base + Nn + nn] = lo;
                    } else if (MODE == 1) {
                        float gl = gelu_f(v);
                        int bb = c >> 5, vd = c & 31;
                        long a = ((long)bb * M + m) * 512 + blockIdx.z * 32 + vd;
                        __nv_bfloat16 hi, lo; split_f(gl, hi, lo);
                        ((__nv_bfloat16*)Cout)[a] = hi;
                        ((__nv_bfloat16*)Cout)[a + 256] = lo;
                    } else if (MODE == 2) {
                        float gl = gelu_f(v + bias[c]);
                        __nv_bfloat16 hi, lo; split_f(gl, hi, lo);
                        ((__nv_bfloat16*)Cout)[(long)m * 512 + c] = hi;
                        ((__nv_bfloat16*)Cout)[(long)m * 512 + 256 + c] = lo;
                    } else if (MODE == 3) {
                        ((float*)Cout)[(long)m * 256 + c] = v + bias[c];
                    } else if (MODE == 4) {
                        float gl = gelu_f(v + bias[c] + other[(long)m * 256 + c]);
                        __nv_bfloat16 hi, lo; split_f(gl, hi, lo);
                        ((__nv_bfloat16*)Cout)[(long)m * 512 + c] = hi;
                        ((__nv_bfloat16*)Cout)[(long)m * 512 + 256 + c] = lo;
                    } else {
                        ((float*)Cout)[(long)m * 256 + c] = gelu_f(v + bias[c]);
                    }
                }
            }
        }
    }
}

// ---------------- final projection ----------------
__global__ void final_k(const float* __restrict__ h, const float* __restrict__ w,
                        const float* __restrict__ b, float* __restrict__ out) {
    int row = blockIdx.x * 8 + (threadIdx.x >> 5);
    int lane = threadIdx.x & 31;
    const float* hr = h + (long)row * CDIM;
    float acc = 0.0f;
    #pragma unroll
    for (int c = lane; c < CDIM; c += 32) acc += hr[c] * w[c];
    #pragma unroll
    for (int o = 16; o > 0; o >>= 1) acc += __shfl_down_sync(0xffffffffu, acc, o);
    if (lane == 0) out[row] = acc + b[0];
}

// ---------------- host orchestration ----------------
static float* sym(const void* s) {
    void* p = nullptr;
    cudaGetSymbolAddress(&p, s);
    return (float*)p;
}

extern "C" void kernel_launch(void* const* d_in, const int* in_sizes, int n_in,
                              void* d_out, int out_size) {
    const float* x         = (const float*)d_in[0];
    const float* m_down    = (const float*)d_in[1];
    const float* m_p0      = (const float*)d_in[2];
    const float* m_p1      = (const float*)d_in[3];
    const float* m_up      = (const float*)d_in[4];
    const float* en_w      = (const float*)d_in[5];
    const float* en_b      = (const float*)d_in[6];
    const float* down_r    = (const float*)d_in[7];
    const float* down_w    = (const float*)d_in[8];
    const float* pa_r[2]   = {(const float*)d_in[9],  (const float*)d_in[17]};
    const float* pa_w[2]   = {(const float*)d_in[10], (const float*)d_in[18]};
    const float* f1w[2]    = {(const float*)d_in[11], (const float*)d_in[19]};
    const float* f1b[2]    = {(const float*)d_in[12], (const float*)d_in[20]};
    const float* f2w[2]    = {(const float*)d_in[13], (const float*)d_in[21]};
    const float* f2b[2]    = {(const float*)d_in[14], (const float*)d_in[22]};
    const float* rw[2]     = {(const float*)d_in[15], (const float*)d_in[23]};
    const float* rb[2]     = {(const float*)d_in[16], (const float*)d_in[24]};
    const float* up_r      = (const float*)d_in[25];
    const float* up_w      = (const float*)d_in[26];
    const float* de1w      = (const float*)d_in[27];
    const float* de1b      = (const float*)d_in[28];
    const float* de2w      = (const float*)d_in[29];
    const float* de2b      = (const float*)d_in[30];
    const float* mdp[2]    = {m_p0, m_p1};

    __nv_bfloat16* h0  = (__nv_bfloat16*)sym(g_bufA);
    float*         de1 = sym(g_bufB);
    __nv_bfloat16* Lb[3] = {(__nv_bfloat16*)sym(g_bufL0), (__nv_bfloat16*)sym(g_bufL1),
                            (__nv_bfloat16*)sym(g_bufL2)};
    float*         mlp32 = sym(g_mlp);
    __nv_bfloat16* attD  = (__nv_bfloat16*)sym(g_attD);
    __nv_bfloat16* attU  = (__nv_bfloat16*)sym(g_attU);
    __nv_bfloat16* attP[2] = {(__nv_bfloat16*)sym(g_attP0), (__nv_bfloat16*)sym(g_attP1)};
    __nv_bfloat16* vtT = (__nv_bfloat16*)sym(g_vt);
    __nv_bfloat16* wt  = (__nv_bfloat16*)sym(g_wt);

    static cudaStream_t s1 = nullptr;
    static cudaEvent_t evFork, evD, evP0, evP1, evU;
    static bool init_done = false;
    if (!init_done) {
        cudaFuncSetAttribute(mma_k<0>, cudaFuncAttributeMaxDynamicSharedMemorySize, SMEM_DYN);
        cudaFuncSetAttribute(mma_k<1>, cudaFuncAttributeMaxDynamicSharedMemorySize, SMEM_DYN);
        cudaFuncSetAttribute(mma_k<2>, cudaFuncAttributeMaxDynamicSharedMemorySize, SMEM_DYN);
        cudaFuncSetAttribute(mma_k<3>, cudaFuncAttributeMaxDynamicSharedMemorySize, SMEM_DYN);
        cudaFuncSetAttribute(mma_k<4>, cudaFuncAttributeMaxDynamicSharedMemorySize, SMEM_DYN);
        cudaFuncSetAttribute(mma_k<5>, cudaFuncAttributeMaxDynamicSharedMemorySize, SMEM_DYN);
        cudaStreamCreateWithFlags(&s1, cudaStreamNonBlocking);
        cudaEventCreateWithFlags(&evFork, cudaEventDisableTiming);
        cudaEventCreateWithFlags(&evD, cudaEventDisableTiming);
        cudaEventCreateWithFlags(&evP0, cudaEventDisableTiming);
        cudaEventCreateWithFlags(&evP1, cudaEventDisableTiming);
        cudaEventCreateWithFlags(&evU, cudaEventDisableTiming);
        init_done = true;
    }

    // ---- fork: softmax/pct chain on s1 (MUFU-bound), overlapping GEMMs on s0 ----
    cudaEventRecord(evFork, 0);
    cudaStreamWaitEvent(s1, evFork, 0);
    softmax_k<NFULL><<<HEADS * NLAT, 256, 0, s1>>>(m_down, down_r, attD, NLAT);
    cudaEventRecord(evD, s1);
    pct_att_k<<<HEADS * NLAT, 256, 0, s1>>>(mdp[0], pa_r[0], attP[0]);
    cudaEventRecord(evP0, s1);
    pct_att_k<<<HEADS * NLAT, 256, 0, s1>>>(mdp[1], pa_r[1], attP[1]);
    cudaEventRecord(evP1, s1);
    softmax_k<NLAT><<<HEADS * NFULL, 256, 0, s1>>>(m_up, up_r, attU, NFULL);
    cudaEventRecord(evU, s1);

    // ---- main stream: encoder + GEMM chain ----
    encoder_k<<<B_SZ * NFULL, 256>>>(x, en_w, en_b, h0);

    // 2. down attention
    cvt_w2_k<<<256, 256>>>(down_w, wt);
    mma_k<0><<<dim3(512, 2, 1), 256, SMEM_DYN>>>(wt, h0, vtT, nullptr, nullptr,
                                                 256, 256, 0, 0, NFULL);
    cudaStreamWaitEvent(0, evD, 0);
    mma_k<1><<<dim3(4, 8, 8), 256, SMEM_DYN>>>(attD, vtT, Lb[0], nullptr, nullptr,
                                               NLAT, NFULL, (long)NLAT * 2 * NFULL,
                                               (long)256 * 2 * NFULL, 0);

    // 3. two latent blocks
    __nv_bfloat16* hcur = Lb[0];
    __nv_bfloat16* s0b = Lb[1];
    __nv_bfloat16* s1b = Lb[2];
    for (int blk = 0; blk < 2; blk++) {
        cvt_w2_k<<<256, 256>>>(pa_w[blk], wt);
        mma_k<0><<<dim3(128, 2, 1), 256, SMEM_DYN>>>(wt, hcur, vtT, nullptr, nullptr,
                                                     256, 256, 0, 0, NLAT);
        cudaStreamWaitEvent(0, blk == 0 ? evP0 : evP1, 0);
        mma_k<1><<<dim3(4, 8, 8), 256, SMEM_DYN>>>(attP[blk], vtT, s0b, nullptr, nullptr,
                                                   NLAT, NLAT, (long)NLAT * 2 * NLAT,
                                                   (long)256 * 2 * NLAT, 0);
        cvt_wT_k<<<256, 256>>>(f1w[blk], wt);
        mma_k<2><<<dim3(4, 64, 1), 256, SMEM_DYN>>>(s0b, wt, s1b, f1b[blk], nullptr,
                                                    B_SZ * NLAT, 256, 0, 0, 0);
        cvt_wT_k<<<256, 256>>>(f2w[blk], wt);
        mma_k<3><<<dim3(4, 64, 1), 256, SMEM_DYN>>>(s1b, wt, mlp32, f2b[blk], nullptr,
                                                    B_SZ * NLAT, 256, 0, 0, 0);
        cvt_wT_k<<<256, 256>>>(rw[blk], wt);
        mma_k<4><<<dim3(4, 64, 1), 256, SMEM_DYN>>>(hcur, wt, s0b, rb[blk], mlp32,
                                                    B_SZ * NLAT, 256, 0, 0, 0);
        __nv_bfloat16* tmp = hcur; hcur = s0b; s0b = tmp;
    }

    // 4. up attention -> h0 hi/lo [B*4096, 512]
    cvt_w2_k<<<256, 256>>>(up_w, wt);
    mma_k<0><<<dim3(128, 2, 1), 256, SMEM_DYN>>>(wt, hcur, vtT, nullptr, nullptr,
                                                 256, 256, 0, 0, NLAT);
    cudaStreamWaitEvent(0, evU, 0);
    mma_k<1><<<dim3(4, 32, 8), 256, SMEM_DYN>>>(attU, vtT, h0, nullptr, nullptr,
                                                NFULL, NLAT, (long)NFULL * 2 * NLAT,
                                                (long)256 * 2 * NLAT, 0);

    // 5. decoder
    cvt_wT_k<<<256, 256>>>(de1w, wt);
    mma_k<5><<<dim3(4, 256, 1), 256, SMEM_DYN>>>(h0, wt, de1, de1b, nullptr,
                                                 B_SZ * NFULL, 256, 0, 0, 0);
    final_k<<<(B_SZ * NFULL) / 8, 256>>>(de1, de2w, de2b, (float*)d_out);
}